// round 9
// baseline (speedup 1.0000x reference)
#include <cuda_runtime.h>
#include <math.h>
#include <stdint.h>

#define BSZ  65536
#define EPSf 1e-5f

// ===================== scratch layout (4-byte units) ========================
#define U_XH  0ull
#define U_XL  (U_XH  + 16777216ull)
#define U_TH  (U_XL  + 16777216ull)
#define U_TL  (U_TH  + 16777216ull)
#define U_YH  (U_TL  + 16777216ull)
#define U_YL  (U_YH  + 8388608ull)
#define U_S   (U_YL  + 8388608ull)
#define U_PS  (U_S   + 65536ull)
#define U_PQ  (U_PS  + 262144ull)
#define U_QP  (U_PQ  + 262144ull)
#define U_AL  (U_QP  + 131072ull)
#define U_BE  (U_AL  + 512ull)
#define U_W1H (U_BE  + 512ull)
#define U_W1L (U_W1H + 131072ull)
#define U_W2H (U_W1L + 131072ull)
#define U_W2L (U_W2H + 65536ull)
#define U_W3H (U_W2L + 65536ull)
#define U_W3L (U_W3H + 65536ull)
#define U_W4H (U_W3L + 65536ull)
#define U_W4L (U_W4H + 131072ull)
#define U_B2F (U_W4L + 131072ull)
#define U_C3  (U_B2F + 256ull)
#define U_NC  (U_C3  + 512ull)
#define U_B4F (U_NC  + 256ull)
#define U_TOT (U_B4F + 512ull)

__device__ __align__(1024) float g_scratch[U_TOT];

// ===================== helpers ==============================================
__device__ __forceinline__ uint32_t smem_u32(const void* p) {
    uint32_t a;
    asm("{ .reg .u64 t; cvta.to.shared.u64 t, %1; cvt.u32.u64 %0, t; }" : "=r"(a) : "l"(p));
    return a;
}
__device__ __forceinline__ void cpa16(uint32_t dst, const void* src) {
    asm volatile("cp.async.cg.shared.global [%0], [%1], 16;" :: "r"(dst), "l"(src) : "memory");
}
__device__ __forceinline__ void cpa_commit() {
    asm volatile("cp.async.commit_group;" ::: "memory");
}
template<int N> __device__ __forceinline__ void cpa_wait() {
    asm volatile("cp.async.wait_group %0;" :: "n"(N) : "memory");
}
__device__ __forceinline__ void ldsm4(uint32_t* r, uint32_t addr) {
    asm volatile("ldmatrix.sync.aligned.m8n8.x4.shared.b16 {%0,%1,%2,%3}, [%4];"
        : "=r"(r[0]), "=r"(r[1]), "=r"(r[2]), "=r"(r[3]) : "r"(addr));
}
__device__ __forceinline__ void mma_bf16(float* d, const uint32_t* a, uint32_t b0, uint32_t b1) {
    asm volatile("mma.sync.aligned.m16n8k16.row.col.f32.bf16.bf16.f32 "
        "{%0,%1,%2,%3}, {%4,%5,%6,%7}, {%8,%9}, {%0,%1,%2,%3};"
        : "+f"(d[0]), "+f"(d[1]), "+f"(d[2]), "+f"(d[3])
        : "r"(a[0]), "r"(a[1]), "r"(a[2]), "r"(a[3]), "r"(b0), "r"(b1));
}
__device__ __forceinline__ uint32_t cvt2bf(float hi, float lo) {
    uint32_t r;
    asm("cvt.rn.bf16x2.f32 %0, %1, %2;" : "=r"(r) : "f"(hi), "f"(lo));
    return r;
}

// ===================== small kernels ========================================
__global__ void k_noise(const float* __restrict__ noise, const float* __restrict__ fir,
                        float* __restrict__ nc_out, float* __restrict__ tail)
{
    __shared__ float v[256];
    int t = threadIdx.x;
    float nstd = (float)sqrt(1.0 / (4.0 * pow(10.0, 0.7)));
    v[t] = noise[t] * nstd;
    __syncthreads();
    float acc = 0.f;
#pragma unroll
    for (int j = 0; j < 100; j++) {
        int idx = t + 49 - j;
        if (idx >= 0 && idx < 256) acc = fmaf(fir[j], v[idx], acc);
    }
    nc_out[t] = acc;
    if (tail) tail[t] = acc;
}

__global__ void k_split4(const float4* __restrict__ W, const float* __restrict__ alpha,
                         uint2* __restrict__ Ph, uint2* __restrict__ Pl,
                         int total4, int kmask)
{
    for (int i = blockIdx.x*blockDim.x + threadIdx.x; i < total4; i += gridDim.x*blockDim.x) {
        float4 v = W[i];
        if (alpha) {
            int k = (4*i) & kmask;
            v.x *= alpha[k]; v.y *= alpha[k+1]; v.z *= alpha[k+2]; v.w *= alpha[k+3];
        }
        uint32_t h0 = cvt2bf(v.y, v.x), h1 = cvt2bf(v.w, v.z);
        float a0 = __uint_as_float(h0 << 16), a1 = __uint_as_float(h0 & 0xFFFF0000u);
        float a2 = __uint_as_float(h1 << 16), a3 = __uint_as_float(h1 & 0xFFFF0000u);
        uint32_t l0 = cvt2bf(v.y - a1, v.x - a0), l1 = cvt2bf(v.w - a3, v.z - a2);
        Ph[i] = make_uint2(h0, h1);
        Pl[i] = make_uint2(l0, l1);
    }
}

__global__ void k_affine(const float* __restrict__ ps, const float* __restrict__ pq,
                         const float* __restrict__ g, const float* __restrict__ bt,
                         float* __restrict__ alpha, float* __restrict__ beta, int np)
{
    int j = blockIdx.x, t = threadIdx.x;   // 128 threads
    float s = 0.f, q = 0.f;
    for (int i = t; i < np; i += 128) { s += ps[j*np + i]; q += pq[j*np + i]; }
    __shared__ float rs[128], rq[128];
    rs[t] = s; rq[t] = q; __syncthreads();
    for (int o = 64; o > 0; o >>= 1) {
        if (t < o) { rs[t] += rs[t+o]; rq[t] += rq[t+o]; }
        __syncthreads();
    }
    if (t == 0) {
        float mu  = rs[0] * (1.f/65536.f);
        float var = rq[0] * (1.f/65536.f) - mu*mu;
        float a = g[j] * rsqrtf(var + EPSf);
        alpha[j] = a; beta[j] = bt[j] - mu*a;
    }
}

__global__ void k_scale(const float* __restrict__ qp, float* __restrict__ s)
{
    int r = blockIdx.x*256 + threadIdx.x;
    s[r] = sqrtf(256.f / (qp[r] + qp[65536 + r]));
}

__global__ void k_fold_b(const float* __restrict__ W, const float* __restrict__ beta,
                         const float* __restrict__ b, float* __restrict__ bf, int K)
{
    int j = blockIdx.x, t = threadIdx.x;
    float acc = 0.f;
    for (int k = t; k < K; k += 128) acc += beta[k] * W[(size_t)j*K + k];
    __shared__ float r[128];
    r[t] = acc; __syncthreads();
    for (int o = 64; o > 0; o >>= 1) { if (t < o) r[t] += r[t+o]; __syncthreads(); }
    if (t == 0) bf[j] = b[j] + r[0];
}

// ===================== HMMA GEMM ============================================
// C[M,N] = epi( A[M,K] @ W[N,K]^T + bias )
// BM=256 BN=128 KC=64, 256 threads, 8 warps (4M x 2N), warp tile 64x64
// MODE 0: +bias, prelu, store planes, col stats partials
// MODE 1: +bias, store planes, row sumsq partials
// MODE 2: rowscale*acc + bias, prelu, store planes, col stats partials
// MODE 3: +bias, store fp32
#define APLB   36864            // A plane bytes: 256 rows * 144
#define WPLB   18432            // W plane bytes: 128 rows * 144
#define BUFB   (2*APLB + 2*WPLB)
#define SMEMSZ (2*BUFB)

template<int MODE>
__global__ void __launch_bounds__(256, 1)
gemm_hmma(const uint32_t* __restrict__ Ah, const uint32_t* __restrict__ Al,
          const uint32_t* __restrict__ Wh, const uint32_t* __restrict__ Wl,
          const float* __restrict__ bias,
          uint32_t* __restrict__ Ch, uint32_t* __restrict__ Cl, float* __restrict__ Cf,
          const float* __restrict__ rowscale, const float* __restrict__ slope_p,
          float* __restrict__ ps, float* __restrict__ pq, float* __restrict__ qp,
          int K, int Ntot)
{
    extern __shared__ __align__(1024) char smem[];
    __shared__ float bias_s[128];
    const uint32_t sb = smem_u32(smem);
    const int tid = threadIdx.x;
    const int wid = tid >> 5, lid = tid & 31;
    const int wm = wid & 3, wn = wid >> 2;
    const int g = lid >> 2, t = lid & 3;
    const int row0 = blockIdx.y * 256;
    const int col0 = blockIdx.x * 128;
    const int nkt = K >> 6;

    if (tid < 128) bias_s[tid] = bias[col0 + tid];

    // chunk loader: 6144 cp.async of 16B
    const char* cAh = (const char*)Ah;  const char* cAl = (const char*)Al;
    const char* cWh = (const char*)Wh;  const char* cWl = (const char*)Wl;

#define LOAD_CHUNK(BUF, KT)                                                       \
    do {                                                                          \
        uint32_t dbase = sb + (BUF)*BUFB;                                         \
        size_t koff = (size_t)(KT)*64*2;                                          \
        _Pragma("unroll")                                                         \
        for (int i = tid; i < 4096; i += 256) {                                   \
            int pl = i >> 11, r = (i >> 3) & 255, sg = i & 7;                     \
            const char* sp = pl ? cAl : cAh;                                      \
            cpa16(dbase + pl*APLB + r*144 + sg*16,                                \
                  sp + ((size_t)(row0 + r)*K)*2 + koff + sg*16);                  \
        }                                                                         \
        _Pragma("unroll")                                                         \
        for (int i = tid; i < 2048; i += 256) {                                   \
            int pl = i >> 10, r = (i >> 3) & 127, sg = i & 7;                     \
            const char* sp = pl ? cWl : cWh;                                      \
            cpa16(dbase + 2*APLB + pl*WPLB + r*144 + sg*16,                       \
                  sp + ((size_t)(col0 + r)*K)*2 + koff + sg*16);                  \
        }                                                                         \
        cpa_commit();                                                             \
    } while (0)

    LOAD_CHUNK(0, 0);

    // ldmatrix lane addressing
    const int lr  = lid & 7;
    const int lb3 = (lid >> 3) & 1;
    const int lb4 = (lid >> 4) & 1;
    uint32_t a_off[4], b_off[4];
#pragma unroll
    for (int mt = 0; mt < 4; mt++)
        a_off[mt] = (uint32_t)((wm*64 + mt*16 + lb3*8 + lr)*144 + lb4*16);
#pragma unroll
    for (int j = 0; j < 4; j++)
        b_off[j] = (uint32_t)((wn*64 + j*16 + lb4*8 + lr)*144 + lb3*16);

    float acc[4][8][4];
#pragma unroll
    for (int mt = 0; mt < 4; mt++)
#pragma unroll
        for (int nt = 0; nt < 8; nt++)
#pragma unroll
            for (int c = 0; c < 4; c++) acc[mt][nt][c] = 0.f;

    for (int kt = 0; kt < nkt; kt++) {
        const int b = kt & 1;
        if (kt + 1 < nkt) { LOAD_CHUNK(1 - b, kt + 1); cpa_wait<1>(); }
        else              { cpa_wait<0>(); }
        __syncthreads();

        const uint32_t sA = sb + b*BUFB;
        const uint32_t sW = sA + 2*APLB;

#pragma unroll
        for (int ks = 0; ks < 4; ks++) {
            const uint32_t ko = ks*32;
            uint32_t ah[4][4], bx[4][4];
            // hi x hi
#pragma unroll
            for (int mt = 0; mt < 4; mt++) ldsm4(ah[mt], sA + a_off[mt] + ko);
#pragma unroll
            for (int j = 0; j < 4; j++)    ldsm4(bx[j], sW + b_off[j] + ko);
#pragma unroll
            for (int j = 0; j < 4; j++)
#pragma unroll
                for (int jj = 0; jj < 2; jj++)
#pragma unroll
                    for (int mt = 0; mt < 4; mt++)
                        mma_bf16(acc[mt][j*2+jj], ah[mt], bx[j][jj*2], bx[j][jj*2+1]);
            // hi x lo
#pragma unroll
            for (int j = 0; j < 4; j++)    ldsm4(bx[j], sW + WPLB + b_off[j] + ko);
#pragma unroll
            for (int j = 0; j < 4; j++)
#pragma unroll
                for (int jj = 0; jj < 2; jj++)
#pragma unroll
                    for (int mt = 0; mt < 4; mt++)
                        mma_bf16(acc[mt][j*2+jj], ah[mt], bx[j][jj*2], bx[j][jj*2+1]);
            // lo x hi
#pragma unroll
            for (int mt = 0; mt < 4; mt++) ldsm4(ah[mt], sA + APLB + a_off[mt] + ko);
#pragma unroll
            for (int j = 0; j < 4; j++)    ldsm4(bx[j], sW + b_off[j] + ko);
#pragma unroll
            for (int j = 0; j < 4; j++)
#pragma unroll
                for (int jj = 0; jj < 2; jj++)
#pragma unroll
                    for (int mt = 0; mt < 4; mt++)
                        mma_bf16(acc[mt][j*2+jj], ah[mt], bx[j][jj*2], bx[j][jj*2+1]);
        }
        __syncthreads();
    }

    // ---------------- epilogue --------------------------------------------
    const float slope = (MODE == 0 || MODE == 2) ? slope_p[0] : 0.f;
    float rsl[4][2];
    if (MODE == 2) {
#pragma unroll
        for (int mt = 0; mt < 4; mt++) {
            rsl[mt][0] = rowscale[row0 + wm*64 + mt*16 + g];
            rsl[mt][1] = rowscale[row0 + wm*64 + mt*16 + g + 8];
        }
    }
    float* col_s  = (float*)smem;        // [4][128]
    float* col_q  = col_s + 512;         // [4][128]
    float* rowred = col_q + 512;         // [2][256]
    float rq[8];
#pragma unroll
    for (int i = 0; i < 8; i++) rq[i] = 0.f;
    const int pitch_u32 = Ntot >> 1;
    const int t2 = t*2;

#pragma unroll
    for (int nt = 0; nt < 8; nt++) {
        const int cl = wn*64 + nt*8 + t2;
        const int c  = col0 + cl;
        const float b0 = bias_s[cl], b1 = bias_s[cl + 1];
        float cse = 0.f, cso = 0.f, cqe = 0.f, cqo = 0.f;
#pragma unroll
        for (int mt = 0; mt < 4; mt++) {
            const int r_lo = row0 + wm*64 + mt*16 + g;
            const int r_hi = r_lo + 8;
            float v0 = acc[mt][nt][0], v1 = acc[mt][nt][1];
            float v2 = acc[mt][nt][2], v3 = acc[mt][nt][3];
            if (MODE == 2) {
                v0 = fmaf(v0, rsl[mt][0], b0); v1 = fmaf(v1, rsl[mt][0], b1);
                v2 = fmaf(v2, rsl[mt][1], b0); v3 = fmaf(v3, rsl[mt][1], b1);
            } else {
                v0 += b0; v1 += b1; v2 += b0; v3 += b1;
            }
            if (MODE == 0 || MODE == 2) {
                v0 = (v0 > 0.f) ? v0 : slope*v0;
                v1 = (v1 > 0.f) ? v1 : slope*v1;
                v2 = (v2 > 0.f) ? v2 : slope*v2;
                v3 = (v3 > 0.f) ? v3 : slope*v3;
                cse += v0 + v2; cso += v1 + v3;
                cqe += v0*v0 + v2*v2; cqo += v1*v1 + v3*v3;
            }
            if (MODE == 1) {
                rq[mt*2]   += v0*v0 + v1*v1;
                rq[mt*2+1] += v2*v2 + v3*v3;
            }
            if (MODE == 3) {
                *(float2*)&Cf[(size_t)r_lo*Ntot + c] = make_float2(v0, v1);
                *(float2*)&Cf[(size_t)r_hi*Ntot + c] = make_float2(v2, v3);
            } else {
                uint32_t h01 = cvt2bf(v1, v0);
                float h0 = __uint_as_float(h01 << 16), h1 = __uint_as_float(h01 & 0xFFFF0000u);
                uint32_t l01 = cvt2bf(v1 - h1, v0 - h0);
                uint32_t h23 = cvt2bf(v3, v2);
                float h2 = __uint_as_float(h23 << 16), h3 = __uint_as_float(h23 & 0xFFFF0000u);
                uint32_t l23 = cvt2bf(v3 - h3, v2 - h2);
                size_t i_lo = (size_t)r_lo*pitch_u32 + (c >> 1);
                size_t i_hi = (size_t)r_hi*pitch_u32 + (c >> 1);
                Ch[i_lo] = h01; Cl[i_lo] = l01;
                Ch[i_hi] = h23; Cl[i_hi] = l23;
            }
        }
        if (MODE == 0 || MODE == 2) {
#pragma unroll
            for (int o = 4; o <= 16; o <<= 1) {
                cse += __shfl_xor_sync(0xFFFFFFFFu, cse, o);
                cso += __shfl_xor_sync(0xFFFFFFFFu, cso, o);
                cqe += __shfl_xor_sync(0xFFFFFFFFu, cqe, o);
                cqo += __shfl_xor_sync(0xFFFFFFFFu, cqo, o);
            }
            if (lid < 4) {
                col_s[wm*128 + cl]     = cse;
                col_s[wm*128 + cl + 1] = cso;
                col_q[wm*128 + cl]     = cqe;
                col_q[wm*128 + cl + 1] = cqo;
            }
        }
    }
    if (MODE == 1) {
#pragma unroll
        for (int i = 0; i < 8; i++) {
            rq[i] += __shfl_xor_sync(0xFFFFFFFFu, rq[i], 1);
            rq[i] += __shfl_xor_sync(0xFFFFFFFFu, rq[i], 2);
        }
        if (t == 0) {
#pragma unroll
            for (int mt = 0; mt < 4; mt++) {
                rowred[wn*256 + wm*64 + mt*16 + g]     = rq[mt*2];
                rowred[wn*256 + wm*64 + mt*16 + g + 8] = rq[mt*2+1];
            }
        }
    }
    if (MODE == 0 || MODE == 1 || MODE == 2) {
        __syncthreads();
        if ((MODE == 0 || MODE == 2) && tid < 128) {
            float s = col_s[tid] + col_s[128 + tid] + col_s[256 + tid] + col_s[384 + tid];
            float q = col_q[tid] + col_q[128 + tid] + col_q[256 + tid] + col_q[384 + tid];
            ps[(size_t)(col0 + tid)*gridDim.y + blockIdx.y] = s;
            pq[(size_t)(col0 + tid)*gridDim.y + blockIdx.y] = q;
        }
        if (MODE == 1)
            qp[(size_t)blockIdx.x*65536 + row0 + tid] = rowred[tid] + rowred[256 + tid];
    }
}

// ===================== launch ================================================
extern "C" void kernel_launch(void* const* d_in, const int* in_sizes, int n_in,
                              void* d_out, int out_size)
{
    const float* x    = (const float*)d_in[0];
    const float* nois = (const float*)d_in[1];
    const float* W1   = (const float*)d_in[2];
    const float* b1   = (const float*)d_in[3];
    const float* a1   = (const float*)d_in[4];
    const float* g1   = (const float*)d_in[5];
    const float* bt1  = (const float*)d_in[6];
    const float* W2   = (const float*)d_in[7];
    const float* b2   = (const float*)d_in[8];
    const float* W3   = (const float*)d_in[9];
    const float* b3   = (const float*)d_in[10];
    const float* a2   = (const float*)d_in[11];
    const float* g2   = (const float*)d_in[12];
    const float* bt2  = (const float*)d_in[13];
    const float* W4   = (const float*)d_in[14];
    const float* b4   = (const float*)d_in[15];
    const float* fir  = (const float*)d_in[16];
    float* out = (float*)d_out;

    float* scr = nullptr;
    cudaGetSymbolAddress((void**)&scr, g_scratch);
    uint32_t* XH = (uint32_t*)(scr + U_XH);  uint32_t* XL = (uint32_t*)(scr + U_XL);
    uint32_t* TH = (uint32_t*)(scr + U_TH);  uint32_t* TL = (uint32_t*)(scr + U_TL);
    uint32_t* YH = (uint32_t*)(scr + U_YH);  uint32_t* YL = (uint32_t*)(scr + U_YL);
    float* S  = scr + U_S;
    float* PS = scr + U_PS;  float* PQ = scr + U_PQ;  float* QP = scr + U_QP;
    float* AL = scr + U_AL;  float* BE = scr + U_BE;
    uint32_t* W1H = (uint32_t*)(scr + U_W1H); uint32_t* W1L = (uint32_t*)(scr + U_W1L);
    uint32_t* W2H = (uint32_t*)(scr + U_W2H); uint32_t* W2L = (uint32_t*)(scr + U_W2L);
    uint32_t* W3H = (uint32_t*)(scr + U_W3H); uint32_t* W3L = (uint32_t*)(scr + U_W3L);
    uint32_t* W4H = (uint32_t*)(scr + U_W4H); uint32_t* W4L = (uint32_t*)(scr + U_W4L);
    float* B2F = scr + U_B2F; float* C3 = scr + U_C3;
    float* NC  = scr + U_NC;  float* B4F = scr + U_B4F;

    cudaFuncSetAttribute(gemm_hmma<0>, cudaFuncAttributeMaxDynamicSharedMemorySize, SMEMSZ);
    cudaFuncSetAttribute(gemm_hmma<1>, cudaFuncAttributeMaxDynamicSharedMemorySize, SMEMSZ);
    cudaFuncSetAttribute(gemm_hmma<2>, cudaFuncAttributeMaxDynamicSharedMemorySize, SMEMSZ);
    cudaFuncSetAttribute(gemm_hmma<3>, cudaFuncAttributeMaxDynamicSharedMemorySize, SMEMSZ);

    long long need = (long long)BSZ*512 + 256;
    float* tail = ((long long)out_size >= need) ? out + (out_size - 256) : nullptr;

    // independent prep
    k_noise<<<1, 256>>>(nois, fir, NC, tail);
    k_split4<<<2048, 256>>>((const float4*)x,  nullptr, (uint2*)XH, (uint2*)XL, 8388608, 511);
    k_split4<<<64, 256>>>((const float4*)W1, nullptr, (uint2*)W1H, (uint2*)W1L, 65536, 511);
    k_split4<<<32, 256>>>((const float4*)W3, nullptr, (uint2*)W3H, (uint2*)W3L, 32768, 255);

    // stage 1: t = prelu(x@W1^T + b1) ; col stats in epilogue
    gemm_hmma<0><<<dim3(4, 256), 256, SMEMSZ>>>(
        XH, XL, W1H, W1L, b1, TH, TL, nullptr, nullptr, a1, PS, PQ, nullptr, 512, 512);
    k_affine<<<512, 128>>>(PS, PQ, g1, bt1, AL, BE, 256);
    k_split4<<<32, 256>>>((const float4*)W2, AL, (uint2*)W2H, (uint2*)W2L, 32768, 511);
    k_fold_b<<<256, 128>>>(W2, BE, b2, B2F, 512);

    // stage 2: y = t_bn @ W2f^T + b2f ; row sumsq partials
    gemm_hmma<1><<<dim3(2, 256), 256, SMEMSZ>>>(
        TH, TL, W2H, W2L, B2F, YH, YL, nullptr, nullptr, nullptr, nullptr, nullptr, QP, 512, 256);
    k_scale<<<256, 256>>>(QP, S);
    k_fold_b<<<512, 128>>>(W3, NC, b3, C3, 256);

    // stage 3: d = prelu(s_i*(y@W3^T) + c3) ; col stats (d reuses x planes)
    gemm_hmma<2><<<dim3(4, 256), 256, SMEMSZ>>>(
        YH, YL, W3H, W3L, C3, XH, XL, nullptr, S, a2, PS, PQ, nullptr, 256, 512);
    k_affine<<<512, 128>>>(PS, PQ, g2, bt2, AL, BE, 256);
    k_split4<<<64, 256>>>((const float4*)W4, AL, (uint2*)W4H, (uint2*)W4L, 65536, 511);
    k_fold_b<<<512, 128>>>(W4, BE, b4, B4F, 512);

    // stage 4: out = d_bn @ W4f^T + b4f (fp32)
    gemm_hmma<3><<<dim3(4, 256), 256, SMEMSZ>>>(
        XH, XL, W4H, W4L, B4F, nullptr, nullptr, out, nullptr, nullptr,
        nullptr, nullptr, nullptr, 512, 512);
}